// round 5
// baseline (speedup 1.0000x reference)
#include <cuda_runtime.h>

#define B_   8
#define T_   2048
#define C_   192
#define TT   64
#define RAD  10
#define NTAP (RAD + 1)
#define HX   (RAD + 3)            // 13: x halo
#define ROWS_X (TT + 2 * HX)      // 90
#define ROWS_U (TT + 2 + 2 * RAD) // 86
#define ROWS_G (TT + 2)           // 66
#define NTH  384
#define SMEM_BYTES ((ROWS_X + ROWS_U + ROWS_G) * C_ * 4)

// Per-channel heat-filter taps F_c(s) (wrapped Gaussian), s = 0..RAD
__device__ float g_filt[C_ * NTAP];

// ---------------------------------------------------------------------------
// Exact per-channel taps:
//   F_c(s) = 1/(2T) + (1/T) * sum_{n=1}^{T-1} exp(-k_c*(n*pi/T)^2) * cos(n*pi*s/T)
// (the 1/(2T) constant applies to EVERY tap; combined with the mode-0 term it
//  makes M[t,t'] = F(t-t') + F(t+t'+1) exactly, with no residual DC)
// ---------------------------------------------------------------------------
__global__ void filt_kernel(const float* __restrict__ k)
{
    const int c   = blockIdx.x;
    const int tid = threadIdx.x;
    const float kc = k[c];
    const float w2 = (float)(9.869604401089358 / (2048.0 * 2048.0)); // (pi/T)^2
    const float a  = kc * w2;

    float acc[NTAP];
#pragma unroll
    for (int s = 0; s < NTAP; s++) acc[s] = 0.f;

    for (int n = 1 + tid; n <= T_ - 1; n += 256) {
        float nf = (float)n;
        float e  = expf(-a * nf * nf);
#pragma unroll
        for (int s = 0; s < NTAP; s++) {
            // n*s < 2^24 -> exact float; /2048 exact -> precise cospi argument
            acc[s] += e * cospif((float)(n * s) * (1.0f / T_));
        }
    }

#pragma unroll
    for (int s = 0; s < NTAP; s++) {
        float v = acc[s];
#pragma unroll
        for (int m = 16; m; m >>= 1) v += __shfl_xor_sync(0xffffffffu, v, m);
        acc[s] = v;
    }

    __shared__ float red[8][NTAP];
    const int wid = tid >> 5, lane = tid & 31;
    if (lane == 0) {
#pragma unroll
        for (int s = 0; s < NTAP; s++) red[wid][s] = acc[s];
    }
    __syncthreads();
    if (tid < NTAP) {
        float sum = 0.f;
#pragma unroll
        for (int q = 0; q < 8; q++) sum += red[q][tid];
        // +1/(2T) on EVERY tap: F(s) = 1/(2T) + (1/T)*sum_{n>=1} ...
        g_filt[c * NTAP + tid] = sum * (1.0f / T_) + 0.5f / T_;
    }
}

// ---------------------------------------------------------------------------
// Fully fused: conv3(depthwise) -> conv3(grouped 1->2) -> heat (wrapped
// Gaussian taps, reflect boundary) -> LayerNorm(C) -> *silu(z)
// -> conv3(depthwise) -> out.
// Block = (time tile of TT, batch). Threads: c = tid%192, tr = tid/192 (2 rows
// per iteration). All smem rows are c-contiguous -> conflict-free.
// ---------------------------------------------------------------------------
__global__ __launch_bounds__(NTH, 1)
void fused_kernel(const float* __restrict__ x,
                  const float* __restrict__ dw, const float* __restrict__ db,
                  const float* __restrict__ lw, const float* __restrict__ lb,
                  const float* __restrict__ gamma, const float* __restrict__ beta,
                  const float* __restrict__ ow, const float* __restrict__ ob,
                  float* __restrict__ out)
{
    extern __shared__ float sm[];
    float* xs = sm;                          // ROWS_X rows
    float* us = sm + ROWS_X * C_;            // ROWS_U rows
    float* gs = sm + (ROWS_X + ROWS_U) * C_; // ROWS_G rows
    __shared__ float redA[12], redB[12];

    const int b   = blockIdx.y;
    const int t0  = blockIdx.x * TT;
    const int tid = threadIdx.x;
    const int c   = tid % C_;
    const int tr  = tid / C_;       // 0 or 1
    const int c2  = c >> 1;         // input channel for u (group mapping)
    const int zc2 = 96 + c2;        // input channel for z

    // ---- per-thread (per-channel) parameters ----
    const float dwu0 = dw[c2 * 3 + 0], dwu1 = dw[c2 * 3 + 1], dwu2 = dw[c2 * 3 + 2];
    const float dbu  = db[c2];
    const float dwz0 = dw[zc2 * 3 + 0], dwz1 = dw[zc2 * 3 + 1], dwz2 = dw[zc2 * 3 + 2];
    const float dbz  = db[zc2];
    const float lwu0 = lw[c * 3 + 0], lwu1 = lw[c * 3 + 1], lwu2 = lw[c * 3 + 2];
    const float lbu  = lb[c];
    const float lwz0 = lw[(C_ + c) * 3 + 0], lwz1 = lw[(C_ + c) * 3 + 1], lwz2 = lw[(C_ + c) * 3 + 2];
    const float lbz  = lb[C_ + c];
    const float ga = gamma[c], be = beta[c];
    const float ow0 = ow[c * 3 + 0], ow1 = ow[c * 3 + 1], ow2 = ow[c * 3 + 2];
    const float obc = ob[c];
    float f[NTAP];
#pragma unroll
    for (int s = 0; s < NTAP; s++) f[s] = g_filt[c * NTAP + s];

    const float* xb = x + (size_t)b * T_ * C_;

    // ---- load x tile (zero-padded outside [0,T)) ----
    for (int i = tr; i < ROWS_X; i += 2) {
        int t = t0 - HX + i;
        xs[i * C_ + c] = (t >= 0 && t < T_) ? xb[(size_t)t * C_ + c] : 0.f;
    }
    __syncthreads();

    // ---- u = conv3(lw_u) o conv3(dw) on channel c2, zero pad between convs ----
    for (int i = tr; i < ROWS_U; i += 2) {
        int t = t0 - (RAD + 1) + i;      // global time; xs row for t is i+2
        float val = 0.f;
        if (t >= 0 && t < T_) {
            float xv0 = xs[(i + 0) * C_ + c2];
            float xv1 = xs[(i + 1) * C_ + c2];
            float xv2 = xs[(i + 2) * C_ + c2];
            float xv3 = xs[(i + 3) * C_ + c2];
            float xv4 = xs[(i + 4) * C_ + c2];
            float h0 = (t - 1 >= 0) ? (dbu + dwu0 * xv0 + dwu1 * xv1 + dwu2 * xv2) : 0.f;
            float h1 =               (dbu + dwu0 * xv1 + dwu1 * xv2 + dwu2 * xv3);
            float h2 = (t + 1 < T_) ? (dbu + dwu0 * xv2 + dwu1 * xv3 + dwu2 * xv4) : 0.f;
            val = lbu + lwu0 * h0 + lwu1 * h1 + lwu2 * h2;
        }
        us[i * C_ + c] = val;
    }
    __syncthreads();

    // ---- heat conv (reflect) + LayerNorm over C + silu(z) gate ----
    const int baseu = t0 - (RAD + 1);
    for (int i = tr; i < ROWS_G; i += 2) {
        int t = t0 - 1 + i;

        // y[t] = sum_{|s|<=R} F(s) * u_reflect[t-s]
        float v = f[0] * us[(i + RAD) * C_ + c];
#pragma unroll
        for (int s = 1; s <= RAD; s++) {
            int tl = t - s; tl = (tl >= 0) ? tl : (-1 - tl);
            int th = t + s; th = (th < T_) ? th : (2 * T_ - 1 - th);
            v += f[s] * (us[(tl - baseu) * C_ + c] + us[(th - baseu) * C_ + c]);
        }

        // LayerNorm reduction: each warp holds 32 channels of one time row
        float s1 = v, s2 = v * v;
#pragma unroll
        for (int m = 16; m; m >>= 1) {
            s1 += __shfl_xor_sync(0xffffffffu, s1, m);
            s2 += __shfl_xor_sync(0xffffffffu, s2, m);
        }
        int w = tid >> 5;
        if ((tid & 31) == 0) { redA[w] = s1; redB[w] = s2; }
        __syncthreads();
        float S1 = 0.f, S2 = 0.f;
#pragma unroll
        for (int q = 0; q < 6; q++) { S1 += redA[tr * 6 + q]; S2 += redB[tr * 6 + q]; }
        float mu  = S1 * (1.0f / C_);
        float var = S2 * (1.0f / C_) - mu * mu;
        float g = (v - mu) * rsqrtf(var + 1e-5f) * ga + be;

        // z gate recomputed from resident x tile (channel zc2)
        float xz0 = xs[(i + 10) * C_ + zc2];
        float xz1 = xs[(i + 11) * C_ + zc2];
        float xz2 = xs[(i + 12) * C_ + zc2];
        float xz3 = xs[(i + 13) * C_ + zc2];
        float xz4 = xs[(i + 14) * C_ + zc2];
        float hz0 = (t - 1 >= 0) ? (dbz + dwz0 * xz0 + dwz1 * xz1 + dwz2 * xz2) : 0.f;
        float hz1 =                (dbz + dwz0 * xz1 + dwz1 * xz2 + dwz2 * xz3);
        float hz2 = (t + 1 < T_) ? (dbz + dwz0 * xz2 + dwz1 * xz3 + dwz2 * xz4) : 0.f;
        float zv  = lbz + lwz0 * hz0 + lwz1 * hz1 + lwz2 * hz2;
        g *= zv * (1.0f / (1.0f + __expf(-zv)));

        gs[i * C_ + c] = (t >= 0 && t < T_) ? g : 0.f;
        __syncthreads();   // protects redA/redB reuse + orders gs for final conv
    }

    // ---- final depthwise conv3 (zero pad) + store ----
    for (int i = tr; i < TT; i += 2) {
        int t = t0 + i;
        float o = obc + ow0 * gs[i * C_ + c]
                      + ow1 * gs[(i + 1) * C_ + c]
                      + ow2 * gs[(i + 2) * C_ + c];
        out[((size_t)b * T_ + t) * C_ + c] = o;
    }
}

// ---------------------------------------------------------------------------
extern "C" void kernel_launch(void* const* d_in, const int* in_sizes, int n_in,
                              void* d_out, int out_size)
{
    const float* x  = (const float*)d_in[0];
    const float* dw = (const float*)d_in[1];
    const float* db = (const float*)d_in[2];
    const float* lw = (const float*)d_in[3];
    const float* lb = (const float*)d_in[4];
    const float* ga = (const float*)d_in[5];
    const float* be = (const float*)d_in[6];
    const float* ow = (const float*)d_in[7];
    const float* ob = (const float*)d_in[8];
    const float* k  = (const float*)d_in[9];
    float* out = (float*)d_out;

    cudaFuncSetAttribute(fused_kernel, cudaFuncAttributeMaxDynamicSharedMemorySize,
                         SMEM_BYTES);

    filt_kernel<<<C_, 256>>>(k);
    fused_kernel<<<dim3(T_ / TT, B_), NTH, SMEM_BYTES>>>(x, dw, db, lw, lb,
                                                         ga, be, ow, ob, out);
}

// round 7
// speedup vs baseline: 2.1805x; 2.1805x over previous
#include <cuda_runtime.h>

#define B_   8
#define T_   2048
#define C_   192
#define TT   32
#define NBX  (T_ / TT)            // 64
#define RAD  10
#define NTAP (RAD + 1)
#define ROWS_X (TT + 26)          // 58
#define ROWS_U (TT + 22)          // 54
#define ROWS_G (TT + 2)           // 34
#define NTH  384
#define SMEM_BYTES ((ROWS_X + ROWS_U + ROWS_G) * C_ * 4)   // 112,128 B

// Per-channel heat-filter taps F_c(s) (wrapped Gaussian), s = 0..RAD
__device__ float g_filt[C_ * NTAP];

// ---------------------------------------------------------------------------
// Exact per-channel taps:
//   F_c(s) = 1/(2T) + (1/T) * sum_{n=1}^{T-1} exp(-k_c*(n*pi/T)^2) * cos(n*pi*s/T)
// ---------------------------------------------------------------------------
__global__ void filt_kernel(const float* __restrict__ k)
{
    const int c   = blockIdx.x;
    const int tid = threadIdx.x;
    const float kc = k[c];
    const float w2 = (float)(9.869604401089358 / (2048.0 * 2048.0)); // (pi/T)^2
    const float a  = kc * w2;

    float acc[NTAP];
#pragma unroll
    for (int s = 0; s < NTAP; s++) acc[s] = 0.f;

    for (int n = 1 + tid; n <= T_ - 1; n += 256) {
        float nf = (float)n;
        float e  = expf(-a * nf * nf);
#pragma unroll
        for (int s = 0; s < NTAP; s++)
            acc[s] += e * cospif((float)(n * s) * (1.0f / T_));
    }

#pragma unroll
    for (int s = 0; s < NTAP; s++) {
        float v = acc[s];
#pragma unroll
        for (int m = 16; m; m >>= 1) v += __shfl_xor_sync(0xffffffffu, v, m);
        acc[s] = v;
    }

    __shared__ float red[8][NTAP];
    const int wid = tid >> 5, lane = tid & 31;
    if (lane == 0) {
#pragma unroll
        for (int s = 0; s < NTAP; s++) red[wid][s] = acc[s];
    }
    __syncthreads();
    if (tid < NTAP) {
        float sum = 0.f;
#pragma unroll
        for (int q = 0; q < 8; q++) sum += red[q][tid];
        g_filt[c * NTAP + tid] = sum * (1.0f / T_) + 0.5f / T_;
    }
}

// ---------------------------------------------------------------------------
// Fused tile body. EDGE=true adds boundary guards (blocks 0 and NBX-1 only).
// ---------------------------------------------------------------------------
template<bool EDGE>
__device__ __forceinline__ void run_tile(
    const float* __restrict__ xb,
    const float* __restrict__ dw, const float* __restrict__ db,
    const float* __restrict__ lw, const float* __restrict__ lb,
    const float* __restrict__ gamma, const float* __restrict__ beta,
    const float* __restrict__ ow, const float* __restrict__ ob,
    float* __restrict__ outb,
    float* xs, float* us, float* vs, float* s_mu, float* s_rs, int t0)
{
    const int tid  = threadIdx.x;
    const int c    = tid % C_;
    const int tr   = tid / C_;     // 0 or 1
    const int c2   = c >> 1;
    const int zc2  = 96 + c2;
    const int lane = tid & 31, wid = tid >> 5;

    const float dwu0 = dw[c2*3+0], dwu1 = dw[c2*3+1], dwu2 = dw[c2*3+2], dbu = db[c2];
    const float lwu0 = lw[c*3+0],  lwu1 = lw[c*3+1],  lwu2 = lw[c*3+2],  lbu = lb[c];
    const float dwz0 = dw[zc2*3+0], dwz1 = dw[zc2*3+1], dwz2 = dw[zc2*3+2], dbz = db[zc2];
    const float lwz0 = lw[(C_+c)*3+0], lwz1 = lw[(C_+c)*3+1], lwz2 = lw[(C_+c)*3+2], lbz = lb[C_+c];
    const float ga = gamma[c], be = beta[c];
    const float ow0 = ow[c*3+0], ow1 = ow[c*3+1], ow2 = ow[c*3+2], obc = ob[c];
    float f[NTAP];
#pragma unroll
    for (int s = 0; s < NTAP; s++) f[s] = g_filt[c*NTAP + s];

    // ---- load x tile ----
#pragma unroll
    for (int i = tr; i < ROWS_X; i += 2) {
        int t = t0 - 13 + i;
        float v;
        if (EDGE) v = (t >= 0 && t < T_) ? xb[(size_t)t*C_ + c] : 0.f;
        else      v = xb[(size_t)t*C_ + c];
        xs[i*C_ + c] = v;
    }
    __syncthreads();

    // ---- u build: contiguous rows [tr*27, +27), sliding h window ----
    {
        const int i0 = tr * 27;
        const int tstart = t0 - 11 + i0;
        float x0 = xs[(i0+0)*C_ + c2];  // x(tstart-2)
        float x1 = xs[(i0+1)*C_ + c2];
        float x2 = xs[(i0+2)*C_ + c2];
        float x3 = xs[(i0+3)*C_ + c2];
        float hm = dbu + dwu0*x0 + dwu1*x1 + dwu2*x2;   // h(tstart-1)
        float hc = dbu + dwu0*x1 + dwu1*x2 + dwu2*x3;   // h(tstart)
        if (EDGE) {
            if (tstart-1 < 0 || tstart-1 >= T_) hm = 0.f;
            if (tstart   < 0 || tstart   >= T_) hc = 0.f;
        }
        float xa = x2, xb2 = x3;
#pragma unroll
        for (int j = 0; j < 27; j++) {
            const int i = i0 + j, t = tstart + j;
            float xn = xs[(i+4)*C_ + c2];               // x(t+2)
            float hp = dbu + dwu0*xa + dwu1*xb2 + dwu2*xn;  // h(t+1)
            if (EDGE && (t+1 < 0 || t+1 >= T_)) hp = 0.f;
            float uv = lbu + lwu0*hm + lwu1*hc + lwu2*hp;
            if (EDGE && (t < 0 || t >= T_)) uv = 0.f;
            us[i*C_ + c] = uv;
            hm = hc; hc = hp; xa = xb2; xb2 = xn;
        }
    }
    __syncthreads();

    // ---- heat conv -> vs ----
    if (!EDGE) {
        // interior: 21-register ring, 1 LDS per output row
        const int i0 = tr * 17;
        float w[21];
#pragma unroll
        for (int s = 0; s < 20; s++) w[s] = us[(i0+s)*C_ + c];
#pragma unroll
        for (int j = 0; j < 17; j++) {
            w[(j+20) % 21] = us[(i0+j+20)*C_ + c];
            float v = f[0] * w[(j+10) % 21];
#pragma unroll
            for (int s = 1; s <= RAD; s++)
                v += f[s] * (w[(j+10-s) % 21] + w[(j+10+s) % 21]);
            vs[(i0+j)*C_ + c] = v;
        }
    } else {
        const int baseu = t0 - 11;
#pragma unroll
        for (int i = tr; i < ROWS_G; i += 2) {
            int t = t0 - 1 + i;
            float v = f[0] * us[(i + RAD)*C_ + c];
#pragma unroll
            for (int s = 1; s <= RAD; s++) {
                int tl = t - s; tl = (tl >= 0) ? tl : (-1 - tl);
                int th = t + s; th = (th < T_) ? th : (2*T_ - 1 - th);
                v += f[s] * (us[(tl - baseu)*C_ + c] + us[(th - baseu)*C_ + c]);
            }
            vs[i*C_ + c] = v;
        }
    }
    __syncthreads();

    // ---- LN stats: warp per row, lane sums 6 stride-32 channels ----
    for (int r = wid; r < ROWS_G; r += 12) {
        float s1 = 0.f, s2 = 0.f;
#pragma unroll
        for (int q = 0; q < 6; q++) {
            float v = vs[r*C_ + lane + 32*q];
            s1 += v; s2 += v*v;
        }
#pragma unroll
        for (int m = 16; m; m >>= 1) {
            s1 += __shfl_xor_sync(0xffffffffu, s1, m);
            s2 += __shfl_xor_sync(0xffffffffu, s2, m);
        }
        if (lane == 0) {
            float mu  = s1 * (1.0f/C_);
            float var = s2 * (1.0f/C_) - mu*mu;
            s_mu[r] = mu;
            s_rs[r] = rsqrtf(var + 1e-5f);
        }
    }
    __syncthreads();

    // ---- gate apply in-place on vs: LN + silu(z), sliding z window ----
    {
        const int i0 = tr * 17;
        const int tstart = t0 - 1 + i0;
        float x0 = xs[(i0+10)*C_ + zc2];   // x(tstart-2)
        float x1 = xs[(i0+11)*C_ + zc2];
        float x2 = xs[(i0+12)*C_ + zc2];
        float x3 = xs[(i0+13)*C_ + zc2];
        float hm = dbz + dwz0*x0 + dwz1*x1 + dwz2*x2;
        float hc = dbz + dwz0*x1 + dwz1*x2 + dwz2*x3;
        if (EDGE) {
            if (tstart-1 < 0 || tstart-1 >= T_) hm = 0.f;
            if (tstart   < 0 || tstart   >= T_) hc = 0.f;
        }
        float xa = x2, xb2 = x3;
#pragma unroll
        for (int j = 0; j < 17; j++) {
            const int i = i0 + j, t = tstart + j;
            float xn = xs[(i+14)*C_ + zc2];
            float hp = dbz + dwz0*xa + dwz1*xb2 + dwz2*xn;
            if (EDGE && (t+1 < 0 || t+1 >= T_)) hp = 0.f;
            float zv = lbz + lwz0*hm + lwz1*hc + lwz2*hp;
            hm = hc; hc = hp; xa = xb2; xb2 = xn;
            float v = vs[i*C_ + c];
            float g = (v - s_mu[i]) * s_rs[i] * ga + be;
            g *= zv * (1.0f / (1.0f + __expf(-zv)));
            if (EDGE && (t < 0 || t >= T_)) g = 0.f;
            vs[i*C_ + c] = g;
        }
    }
    __syncthreads();

    // ---- final conv3 + coalesced store: rows [tr*16, +16) ----
    {
        const int i0 = tr * 16;
        float g0 = vs[(i0+0)*C_ + c];
        float g1 = vs[(i0+1)*C_ + c];
#pragma unroll
        for (int j = 0; j < 16; j++) {
            const int i = i0 + j;
            float g2 = vs[(i+2)*C_ + c];
            outb[(size_t)(t0 + i)*C_ + c] = obc + ow0*g0 + ow1*g1 + ow2*g2;
            g0 = g1; g1 = g2;
        }
    }
}

// ---------------------------------------------------------------------------
__global__ __launch_bounds__(NTH, 2)
void fused_kernel(const float* __restrict__ x,
                  const float* __restrict__ dw, const float* __restrict__ db,
                  const float* __restrict__ lw, const float* __restrict__ lb,
                  const float* __restrict__ gamma, const float* __restrict__ beta,
                  const float* __restrict__ ow, const float* __restrict__ ob,
                  float* __restrict__ out)
{
    extern __shared__ float sm[];
    float* xs = sm;
    float* us = sm + ROWS_X * C_;
    float* vs = sm + (ROWS_X + ROWS_U) * C_;
    __shared__ float s_mu[ROWS_G], s_rs[ROWS_G];

    const int b  = blockIdx.y;
    const int bx = blockIdx.x;
    const int t0 = bx * TT;
    const float* xb   = x   + (size_t)b * T_ * C_;
    float*       outb = out + (size_t)b * T_ * C_;

    if (bx == 0 || bx == NBX - 1)
        run_tile<true >(xb, dw, db, lw, lb, gamma, beta, ow, ob, outb,
                        xs, us, vs, s_mu, s_rs, t0);
    else
        run_tile<false>(xb, dw, db, lw, lb, gamma, beta, ow, ob, outb,
                        xs, us, vs, s_mu, s_rs, t0);
}

// ---------------------------------------------------------------------------
extern "C" void kernel_launch(void* const* d_in, const int* in_sizes, int n_in,
                              void* d_out, int out_size)
{
    const float* x  = (const float*)d_in[0];
    const float* dw = (const float*)d_in[1];
    const float* db = (const float*)d_in[2];
    const float* lw = (const float*)d_in[3];
    const float* lb = (const float*)d_in[4];
    const float* ga = (const float*)d_in[5];
    const float* be = (const float*)d_in[6];
    const float* ow = (const float*)d_in[7];
    const float* ob = (const float*)d_in[8];
    const float* k  = (const float*)d_in[9];
    float* out = (float*)d_out;

    cudaFuncSetAttribute(fused_kernel, cudaFuncAttributeMaxDynamicSharedMemorySize,
                         SMEM_BYTES);

    filt_kernel<<<C_, 256>>>(k);
    fused_kernel<<<dim3(NBX, B_), NTH, SMEM_BYTES>>>(x, dw, db, lw, lb,
                                                     ga, be, ow, ob, out);
}

// round 8
// speedup vs baseline: 2.6831x; 1.2305x over previous
#include <cuda_runtime.h>

typedef unsigned long long ull;

#define B_   8
#define T_   2048
#define C_   192
#define NP   96                   // channel pairs
#define TT   32
#define NBX  (T_ / TT)            // 64
#define RAD  10
#define NTAP (RAD + 1)
#define ROWS_X 58                 // TT + 26
#define ROWS_U 54                 // TT + 22
#define ROWS_G 34                 // TT + 2
#define NTH  384
#define SMEM_BYTES ((ROWS_X + ROWS_U + ROWS_G) * C_ * 4)   // 112,128 B

// ---- packed f32x2 helpers ----
__device__ __forceinline__ ull pk2(float lo, float hi) {
    ull r; asm("mov.b64 %0, {%1, %2};" : "=l"(r) : "f"(lo), "f"(hi)); return r;
}
__device__ __forceinline__ void up2(ull v, float& lo, float& hi) {
    asm("mov.b64 {%0, %1}, %2;" : "=f"(lo), "=f"(hi) : "l"(v));
}
__device__ __forceinline__ ull fma2(ull a, ull b, ull c) {
    ull d; asm("fma.rn.f32x2 %0, %1, %2, %3;" : "=l"(d) : "l"(a), "l"(b), "l"(c)); return d;
}
__device__ __forceinline__ ull add2(ull a, ull b) {
    ull d; asm("add.rn.f32x2 %0, %1, %2;" : "=l"(d) : "l"(a), "l"(b)); return d;
}
__device__ __forceinline__ ull mul2(ull a, ull b) {
    ull d; asm("mul.rn.f32x2 %0, %1, %2;" : "=l"(d) : "l"(a), "l"(b)); return d;
}

// ---------------------------------------------------------------------------
// Fused tile body. EDGE=true adds boundary guards (blocks 0 and NBX-1 only).
// Thread = (channel pair p, row partition tr in 0..3).
// ---------------------------------------------------------------------------
template<bool EDGE>
__device__ __forceinline__ void run_tile(
    const float* __restrict__ xb,
    const float* __restrict__ dw, const float* __restrict__ db,
    const float* __restrict__ lw, const float* __restrict__ lb,
    const float* __restrict__ gamma, const float* __restrict__ beta,
    const float* __restrict__ ow, const float* __restrict__ ob,
    const float* __restrict__ kk,
    float* __restrict__ outb,
    float* sm, float* s_mu, float* s_rs, int t0)
{
    float* xs_f = sm;
    ull*   xs2  = (ull*)sm;
    float* us_f = sm + ROWS_X * C_;
    ull*   us2  = (ull*)us_f;
    ull*   vs2  = (ull*)(sm + (ROWS_X + ROWS_U) * C_);
    float* vs_f = (float*)vs2;

    const int tid  = threadIdx.x;
    const int p    = tid % NP;     // channel pair: channels 2p, 2p+1
    const int tr   = tid / NP;     // 0..3
    const int lane = tid & 31, wid = tid >> 5;
    const int c0 = 2 * p, c1 = 2 * p + 1;

    const ull* xg = (const ull*)xb;   // [t][NP] float2

    // ================= phase 1: x tile load =================
#pragma unroll
    for (int i = tr; i < ROWS_X; i += 4) {
        int t = t0 - 13 + i;
        ull v = 0ull;
        if (!EDGE || (t >= 0 && t < T_)) v = xg[(size_t)t * NP + p];
        xs2[i * NP + p] = v;
    }
    __syncthreads();

    // ================= phase 2: u build (scalar h chain, packed u) ==========
    {
        const float dwu0 = dw[p*3+0], dwu1 = dw[p*3+1], dwu2 = dw[p*3+2], dbu = db[p];
        const ull lwu0_2 = pk2(lw[c0*3+0], lw[c1*3+0]);
        const ull lwu1_2 = pk2(lw[c0*3+1], lw[c1*3+1]);
        const ull lwu2_2 = pk2(lw[c0*3+2], lw[c1*3+2]);
        const ull lbu2   = pk2(lb[c0], lb[c1]);

        const int j0 = (tr == 0) ? 0 : (tr == 1) ? 13 : (tr == 2) ? 27 : 40;
        const int tstart = t0 - 11 + j0;
        float xw0 = xs_f[(j0+0)*C_ + p];
        float xw1 = xs_f[(j0+1)*C_ + p];
        float xw2 = xs_f[(j0+2)*C_ + p];
        float xw3 = xs_f[(j0+3)*C_ + p];
        float hm = dbu + dwu0*xw0 + dwu1*xw1 + dwu2*xw2;   // h(tstart-1)
        float hc = dbu + dwu0*xw1 + dwu1*xw2 + dwu2*xw3;   // h(tstart)
        if (EDGE) {
            if (tstart-1 < 0 || tstart-1 >= T_) hm = 0.f;
            if (tstart   < 0 || tstart   >= T_) hc = 0.f;
        }
        ull hm2 = pk2(hm, hm), hc2 = pk2(hc, hc);
        float xa = xw2, xb2 = xw3;
#pragma unroll
        for (int j = 0; j < 14; j++) {
            const int jr = j0 + j, t = tstart + j;
            float xn = xs_f[(jr+4)*C_ + p];
            float hp = dbu + dwu0*xa + dwu1*xb2 + dwu2*xn;  // h(t+1)
            if (EDGE && (t+1 < 0 || t+1 >= T_)) hp = 0.f;
            ull hp2 = pk2(hp, hp);
            ull u2 = fma2(lwu0_2, hm2, fma2(lwu1_2, hc2, fma2(lwu2_2, hp2, lbu2)));
            if (EDGE && (t < 0 || t >= T_)) u2 = 0ull;
            us2[jr * NP + p] = u2;
            hm2 = hc2; hc2 = hp2; xa = xb2; xb2 = xn;
        }
    }
    __syncthreads();

    // ================= taps (closed-form wrapped Gaussian) ==================
    // F_c(s) = exp(-s^2/(4k)) / (2*sqrt(pi*k))
    ull f2[NTAP];
    {
        const float PI = 3.14159265358979f;
        float klo = kk[c0], khi = kk[c1];
        float alo = 0.5f * rsqrtf(PI * klo), ahi = 0.5f * rsqrtf(PI * khi);
        float ilo = 0.25f / klo,             ihi = 0.25f / khi;
#pragma unroll
        for (int s = 0; s < NTAP; s++) {
            float ss = (float)(s * s);
            f2[s] = pk2(alo * expf(-ss * ilo), ahi * expf(-ss * ihi));
        }
    }

    // ================= phase 3: heat conv -> vs =============================
    const int r0 = (tr == 0) ? 0 : (8 * tr + 1);   // 0, 9, 17, 25 (9 rows each)
    if (!EDGE) {
        ull w[21];
#pragma unroll
        for (int s = 0; s < 20; s++) w[s] = us2[(r0+s)*NP + p];
#pragma unroll
        for (int j = 0; j < 9; j++) {
            w[(j+20) % 21] = us2[(r0+j+20)*NP + p];
            ull v = mul2(f2[0], w[(j+10) % 21]);
#pragma unroll
            for (int s = 1; s <= RAD; s++)
                v = fma2(f2[s], add2(w[(j+10-s) % 21], w[(j+10+s) % 21]), v);
            vs2[(r0+j)*NP + p] = v;
        }
    } else {
        const int baseu = t0 - 11;
#pragma unroll
        for (int j = 0; j < 9; j++) {
            const int r = r0 + j, t = t0 - 1 + r;
            ull v = mul2(f2[0], us2[(r+RAD)*NP + p]);
#pragma unroll
            for (int s = 1; s <= RAD; s++) {
                int tl = t - s; tl = (tl >= 0) ? tl : (-1 - tl);
                int th = t + s; th = (th < T_) ? th : (2*T_ - 1 - th);
                v = fma2(f2[s], add2(us2[(tl-baseu)*NP + p], us2[(th-baseu)*NP + p]), v);
            }
            vs2[r*NP + p] = v;
        }
    }
    __syncthreads();

    // ================= phase 4: LN stats (warp per row) =====================
#pragma unroll
    for (int r = wid; r < ROWS_G; r += 12) {
        float s1 = 0.f, s2 = 0.f;
#pragma unroll
        for (int q = 0; q < 3; q++) {
            float lo, hi;
            up2(vs2[r*NP + lane + 32*q], lo, hi);
            s1 += lo + hi; s2 += lo*lo + hi*hi;
        }
#pragma unroll
        for (int m = 16; m; m >>= 1) {
            s1 += __shfl_xor_sync(0xffffffffu, s1, m);
            s2 += __shfl_xor_sync(0xffffffffu, s2, m);
        }
        if (lane == 0) {
            float mu  = s1 * (1.0f/C_);
            float var = s2 * (1.0f/C_) - mu*mu;
            s_mu[r] = mu;
            s_rs[r] = rsqrtf(var + 1e-5f);
        }
    }
    __syncthreads();

    // ================= phase 5: gate (LN apply + silu(z)), exclusive rows ===
    {
        const int zp = NP + p;   // z input channel
        const float dwz0 = dw[zp*3+0], dwz1 = dw[zp*3+1], dwz2 = dw[zp*3+2], dbz = db[zp];
        const ull lwz0_2 = pk2(lw[(C_+c0)*3+0], lw[(C_+c1)*3+0]);
        const ull lwz1_2 = pk2(lw[(C_+c0)*3+1], lw[(C_+c1)*3+1]);
        const ull lwz2_2 = pk2(lw[(C_+c0)*3+2], lw[(C_+c1)*3+2]);
        const ull lbz2   = pk2(lb[C_+c0], lb[C_+c1]);
        const ull ga2 = pk2(gamma[c0], gamma[c1]);
        const ull be2 = pk2(beta[c0], beta[c1]);

        // exclusive partitions: starts {0,9,17,25}, counts {9,8,8,9}
        const int g0r = r0;
        const int cnt = (tr == 0 || tr == 3) ? 9 : 8;
        const int tstart = t0 - 1 + g0r;
        float xw0 = xs_f[(g0r+10)*C_ + zp];
        float xw1 = xs_f[(g0r+11)*C_ + zp];
        float xw2 = xs_f[(g0r+12)*C_ + zp];
        float xw3 = xs_f[(g0r+13)*C_ + zp];
        float hm = dbz + dwz0*xw0 + dwz1*xw1 + dwz2*xw2;
        float hc = dbz + dwz0*xw1 + dwz1*xw2 + dwz2*xw3;
        if (EDGE) {
            if (tstart-1 < 0 || tstart-1 >= T_) hm = 0.f;
            if (tstart   < 0 || tstart   >= T_) hc = 0.f;
        }
        ull hm2 = pk2(hm, hm), hc2 = pk2(hc, hc);
        float xa = xw2, xb2 = xw3;
#pragma unroll
        for (int j = 0; j < 9; j++) {
            if (j < cnt) {
                const int r = g0r + j, t = tstart + j;
                float xn = xs_f[(r+14)*C_ + zp];
                float hp = dbz + dwz0*xa + dwz1*xb2 + dwz2*xn;
                if (EDGE && (t+1 < 0 || t+1 >= T_)) hp = 0.f;
                ull hp2 = pk2(hp, hp);
                ull zv2 = fma2(lwz0_2, hm2, fma2(lwz1_2, hc2, fma2(lwz2_2, hp2, lbz2)));
                hm2 = hc2; hc2 = hp2; xa = xb2; xb2 = xn;

                float mu = s_mu[r], rs = s_rs[r];
                ull v2 = vs2[r*NP + p];
                ull g2 = fma2(mul2(add2(v2, pk2(-mu, -mu)), pk2(rs, rs)), ga2, be2);

                float zl, zh; up2(zv2, zl, zh);
                float sl = zl * (1.0f / (1.0f + __expf(-zl)));
                float sh = zh * (1.0f / (1.0f + __expf(-zh)));
                ull gated = mul2(g2, pk2(sl, sh));
                if (EDGE && (t < 0 || t >= T_)) gated = 0ull;
                vs2[r*NP + p] = gated;
            }
        }
    }
    __syncthreads();

    // ================= phase 6: final conv3 + store =========================
    {
        const ull ow0_2 = pk2(ow[c0*3+0], ow[c1*3+0]);
        const ull ow1_2 = pk2(ow[c0*3+1], ow[c1*3+1]);
        const ull ow2_2 = pk2(ow[c0*3+2], ow[c1*3+2]);
        const ull ob2   = pk2(ob[c0], ob[c1]);
        ull* outg = (ull*)outb;

        const int q0 = tr * 8;
        ull g0 = vs2[(q0+0)*NP + p];
        ull g1 = vs2[(q0+1)*NP + p];
#pragma unroll
        for (int j = 0; j < 8; j++) {
            ull gnew = vs2[(q0+j+2)*NP + p];
            ull o = fma2(ow0_2, g0, fma2(ow1_2, g1, fma2(ow2_2, gnew, ob2)));
            outg[(size_t)(t0 + q0 + j)*NP + p] = o;
            g0 = g1; g1 = gnew;
        }
    }
}

// ---------------------------------------------------------------------------
__global__ __launch_bounds__(NTH, 2)
void fused_kernel(const float* __restrict__ x,
                  const float* __restrict__ dw, const float* __restrict__ db,
                  const float* __restrict__ lw, const float* __restrict__ lb,
                  const float* __restrict__ gamma, const float* __restrict__ beta,
                  const float* __restrict__ ow, const float* __restrict__ ob,
                  const float* __restrict__ kk,
                  float* __restrict__ out)
{
    extern __shared__ float sm[];
    __shared__ float s_mu[ROWS_G], s_rs[ROWS_G];

    const int b  = blockIdx.y;
    const int bx = blockIdx.x;
    const int t0 = bx * TT;
    const float* xb   = x   + (size_t)b * T_ * C_;
    float*       outb = out + (size_t)b * T_ * C_;

    if (bx == 0 || bx == NBX - 1)
        run_tile<true >(xb, dw, db, lw, lb, gamma, beta, ow, ob, kk, outb,
                        sm, s_mu, s_rs, t0);
    else
        run_tile<false>(xb, dw, db, lw, lb, gamma, beta, ow, ob, kk, outb,
                        sm, s_mu, s_rs, t0);
}

// ---------------------------------------------------------------------------
extern "C" void kernel_launch(void* const* d_in, const int* in_sizes, int n_in,
                              void* d_out, int out_size)
{
    const float* x  = (const float*)d_in[0];
    const float* dw = (const float*)d_in[1];
    const float* db = (const float*)d_in[2];
    const float* lw = (const float*)d_in[3];
    const float* lb = (const float*)d_in[4];
    const float* ga = (const float*)d_in[5];
    const float* be = (const float*)d_in[6];
    const float* ow = (const float*)d_in[7];
    const float* ob = (const float*)d_in[8];
    const float* k  = (const float*)d_in[9];
    float* out = (float*)d_out;

    cudaFuncSetAttribute(fused_kernel, cudaFuncAttributeMaxDynamicSharedMemorySize,
                         SMEM_BYTES);

    fused_kernel<<<dim3(NBX, B_), NTH, SMEM_BYTES>>>(x, dw, db, lw, lb,
                                                     ga, be, ow, ob, k, out);
}